// round 12
// baseline (speedup 1.0000x reference)
#include <cuda_runtime.h>
#include <math.h>

#define B_      8
#define TNEW    512
#define DMODEL  1024
#define H_      16
#define DH      64
#define CACHED  2048
#define TTOTAL  2560
#define MROWS   (B_*TNEW)      // 4096
#define QKVN    3072

#define OFF_K   (MROWS*DMODEL)               // 4194304
#define OFF_V   (OFF_K + B_*H_*TTOTAL*DH)    // 25165824
#define OFF_LEN (OFF_V + B_*H_*TTOTAL*DH)    // 46137344

#define WSZ     (DMODEL*DMODEL)              // 1048576

// Scratch (allocation-free rule: __device__ globals)
__device__ float g_qkv[MROWS*QKVN];        // raw q|k|v projections [4096][3072]
__device__ float g_q  [B_*H_*TNEW*DH];     // roped q (tf32, pre-scaled by 1/8)
__device__ float g_kt [B_*H_*TTOTAL*DH];   // tf32 copy of k_total
__device__ float g_vt [B_*H_*TTOTAL*DH];   // tf32 copy of v_total
__device__ float g_ctx[MROWS*DMODEL];      // attention context (tf32 values)
__device__ float g_xt [MROWS*DMODEL];      // tf32 copy of x_new
__device__ float g_wt [4*WSZ];             // tf32 copies of Wq|Wk|Wv|Wo
__device__ int   g_counts[B_];
__device__ int   g_totals[B_];

// ---------------------------------------------------------------------------
// tf32 / cp.async helpers
// ---------------------------------------------------------------------------
__device__ __forceinline__ float t32(float f) {
    unsigned u;
    asm("cvt.rna.tf32.f32 %0, %1;" : "=r"(u) : "f"(f));
    return __uint_as_float(u);
}
__device__ __forceinline__ unsigned U(float f) { return __float_as_uint(f); }

__device__ __forceinline__ void mma8(float* c, const unsigned* a, const unsigned* b) {
    asm volatile(
        "mma.sync.aligned.m16n8k8.row.col.f32.tf32.tf32.f32 "
        "{%0,%1,%2,%3},{%4,%5,%6,%7},{%8,%9},{%0,%1,%2,%3};"
        : "+f"(c[0]), "+f"(c[1]), "+f"(c[2]), "+f"(c[3])
        : "r"(a[0]), "r"(a[1]), "r"(a[2]), "r"(a[3]), "r"(b[0]), "r"(b[1]));
}

__device__ __forceinline__ void cpa16(float* smem, const float* g) {
    unsigned s = (unsigned)__cvta_generic_to_shared(smem);
    asm volatile("cp.async.cg.shared.global [%0], [%1], 16;" :: "r"(s), "l"(g));
}
__device__ __forceinline__ void cpa_commit() { asm volatile("cp.async.commit_group;"); }
__device__ __forceinline__ void cpa_wait1()  { asm volatile("cp.async.wait_group 1;"); }
__device__ __forceinline__ void cpa_wait0()  { asm volatile("cp.async.wait_group 0;"); }

// ---------------------------------------------------------------------------
// Kernel 0: one-time tf32 pre-conversion of X and W matrices
// ---------------------------------------------------------------------------
__global__ __launch_bounds__(256) void k_cvt(
    const float* __restrict__ X,
    const float* __restrict__ Wq, const float* __restrict__ Wk,
    const float* __restrict__ Wv, const float* __restrict__ Wo)
{
    int idx = blockIdx.x * 256 + threadIdx.x;     // float4 index
    const int XQ = MROWS*DMODEL/4;
    float4 v; float4* dst;
    if (idx < XQ) {
        v = ((const float4*)X)[idx];
        dst = (float4*)g_xt + idx;
    } else {
        int r = idx - XQ;
        int w = r / (WSZ/4);
        int o = r % (WSZ/4);
        const float* src = (w == 0) ? Wq : (w == 1) ? Wk : (w == 2) ? Wv : Wo;
        v = ((const float4*)src)[o];
        dst = (float4*)(g_wt + (size_t)w*WSZ) + o;
    }
    float4 ov = { t32(v.x), t32(v.y), t32(v.z), t32(v.w) };
    *dst = ov;
}

// ---------------------------------------------------------------------------
// Kernel 1: derive new_counts from valid_new_mask (dtype-probed), totals
// ---------------------------------------------------------------------------
__global__ void k_setup(const unsigned char* __restrict__ mask,
                        const int* __restrict__ past_len,
                        float* __restrict__ out_len)
{
    int b = blockIdx.x;
    int lane = threadIdx.x;
    bool bytemode = (mask[7*TNEW + 1] != 0);
    int cnt = 0;
    for (int t = lane; t < TNEW; t += 32) {
        int nz;
        if (bytemode) nz = (mask[b*TNEW + t] != 0);
        else          nz = (((const int*)mask)[b*TNEW + t] != 0);
        cnt += nz;
    }
    #pragma unroll
    for (int o = 16; o; o >>= 1) cnt += __shfl_xor_sync(0xffffffffu, cnt, o);
    if (lane == 0) {
        g_counts[b] = cnt;
        int tot = past_len[b] + cnt;
        g_totals[b] = tot;
        out_len[b] = (float)tot;
    }
}

// ---------------------------------------------------------------------------
// Accurate RoPE angles (fp64 range reduction, fp32 sincos)
// ---------------------------------------------------------------------------
__device__ __forceinline__ void rope_sc(int pos, float fi, float& sn, float& cs)
{
    double f = (double)pos * (double)fi;
    double k = floor(f * 0.15915494309189535);
    float fr = (float)(f - k * 6.283185307179586);
    sincosf(fr, &sn, &cs);
}

// ---------------------------------------------------------------------------
// Shared GEMM body: 128x128 tile, ktile 32, 2-stage cp.async pipeline.
// Inputs are PRE-CONVERTED tf32 -> zero cvt in the loop, raw fragment loads.
// ---------------------------------------------------------------------------
#define GST 36
#define GSTAGE (128*GST)

__device__ __forceinline__ void gemm_pipe(
    const float* __restrict__ Ag, const float* __restrict__ Bg,
    float* sA, float* sB, int tid, float acc[2][8][4])
{
    int warp = tid >> 5, lane = tid & 31;
    int wm = warp >> 1, wn = warp & 1;
    int r0 = lane >> 2, c0 = lane & 3;
    int lrow = tid >> 3;
    int lcol = (tid & 7) * 4;

    #pragma unroll
    for (int it = 0; it < 4; it++) {
        int row = it*32 + lrow;
        cpa16(&sA[row*GST + lcol], &Ag[(size_t)row*DMODEL + lcol]);
        cpa16(&sB[row*GST + lcol], &Bg[(size_t)row*DMODEL + lcol]);
    }
    cpa_commit();

    for (int kt = 0; kt < 32; kt++) {
        int st = (kt & 1) * GSTAGE;
        if (kt + 1 < 32) {
            int ns = ((kt + 1) & 1) * GSTAGE;
            int k0 = (kt + 1) * 32;
            #pragma unroll
            for (int it = 0; it < 4; it++) {
                int row = it*32 + lrow;
                cpa16(&sA[ns + row*GST + lcol], &Ag[(size_t)row*DMODEL + k0 + lcol]);
                cpa16(&sB[ns + row*GST + lcol], &Bg[(size_t)row*DMODEL + k0 + lcol]);
            }
            cpa_commit();
            cpa_wait1();
        } else {
            cpa_wait0();
        }
        __syncthreads();

        #pragma unroll
        for (int ks = 0; ks < 4; ks++) {
            int kk = ks*8;
            unsigned a[2][4], b[8][2];
            #pragma unroll
            for (int mt = 0; mt < 2; mt++) {
                int mr = wm*32 + mt*16 + r0;
                a[mt][0] = U(sA[st + (mr    )*GST + kk + c0]);
                a[mt][1] = U(sA[st + (mr + 8)*GST + kk + c0]);
                a[mt][2] = U(sA[st + (mr    )*GST + kk + 4 + c0]);
                a[mt][3] = U(sA[st + (mr + 8)*GST + kk + 4 + c0]);
            }
            #pragma unroll
            for (int nt = 0; nt < 8; nt++) {
                int nr = wn*64 + nt*8 + r0;
                b[nt][0] = U(sB[st + nr*GST + kk + c0]);
                b[nt][1] = U(sB[st + nr*GST + kk + 4 + c0]);
            }
            #pragma unroll
            for (int mt = 0; mt < 2; mt++)
                #pragma unroll
                for (int nt = 0; nt < 8; nt++)
                    mma8(acc[mt][nt], a[mt], b[nt]);
        }
        __syncthreads();
    }
}

// ---------------------------------------------------------------------------
// Kernel 2: QKV projection (pipelined, zero-cvt). Dead-row blocks exit.
// ---------------------------------------------------------------------------
__global__ __launch_bounds__(256) void k_gemm_qkv(
    const float* __restrict__ bq, const float* __restrict__ bk, const float* __restrict__ bv)
{
    extern __shared__ float smem_g[];
    float* sA = smem_g;
    float* sB = smem_g + 2*GSTAGE;

    int bm = blockIdx.y * 128;
    if ((bm & 511) >= g_counts[bm >> 9]) return;

    int bn = blockIdx.x * 128;
    int seg = bn >> 10;
    const float* bias = (seg == 0) ? bq : ((seg == 1) ? bk : bv);
    int nl = bn & 1023;
    int tid = threadIdx.x;
    int warp = tid >> 5, lane = tid & 31;
    int wm = warp >> 1, wn = warp & 1;
    int r0 = lane >> 2, c0 = lane & 3;

    float acc[2][8][4];
    #pragma unroll
    for (int mt = 0; mt < 2; mt++)
        #pragma unroll
        for (int nt = 0; nt < 8; nt++)
            #pragma unroll
            for (int r = 0; r < 4; r++) acc[mt][nt][r] = 0.f;

    gemm_pipe(g_xt + (size_t)bm*DMODEL,
              g_wt + (size_t)seg*WSZ + (size_t)nl*DMODEL,
              sA, sB, tid, acc);

    #pragma unroll
    for (int mt = 0; mt < 2; mt++) {
        #pragma unroll
        for (int nt = 0; nt < 8; nt++) {
            int row = bm + wm*32 + mt*16 + r0;
            int col = bn + wn*64 + nt*8 + 2*c0;
            float bx = bias[col & 1023], by = bias[(col+1) & 1023];
            float2 v0 = { acc[mt][nt][0] + bx, acc[mt][nt][1] + by };
            float2 v1 = { acc[mt][nt][2] + bx, acc[mt][nt][3] + by };
            *(float2*)&g_qkv[(size_t)row*QKVN + col]     = v0;
            *(float2*)&g_qkv[(size_t)(row+8)*QKVN + col] = v1;
        }
    }
}

// ---------------------------------------------------------------------------
// Kernel 3 (fused): assemble k_total/v_total + RoPE on q.
// tf32 mirrors written only up to roundup(tot,64) (attention never reads past).
// ---------------------------------------------------------------------------
__global__ __launch_bounds__(256) void k_prep(
    const float* __restrict__ pastk, const float* __restrict__ pastv,
    const float* __restrict__ invf, const int* __restrict__ past_len,
    float* __restrict__ out)
{
    int bh = blockIdx.y; int b = bh >> 4; int h = bh & 15;
    int gid = blockIdx.x * 256 + threadIdx.x;
    int i = gid & 31; int s = gid >> 5;
    int pl = past_len[b]; int tot = g_totals[b]; int cnt = g_counts[b];
    float k0, k1, v0, v1;
    if (s < pl) {
        size_t base = ((size_t)bh*CACHED + s) * DH;
        k0 = pastk[base + i]; k1 = pastk[base + i + 32];
        v0 = pastv[base + i]; v1 = pastv[base + i + 32];
    } else if (s < tot) {
        int t = s - pl;
        size_t m = (size_t)(b*TNEW + t) * QKVN;
        float sn, cs; rope_sc(s, invf[i], sn, cs);
        float x0 = g_qkv[m + 1024 + h*DH + i];
        float x1 = g_qkv[m + 1024 + h*DH + i + 32];
        k0 = x0*cs - x1*sn;
        k1 = x1*cs + x0*sn;
        v0 = g_qkv[m + 2048 + h*DH + i];
        v1 = g_qkv[m + 2048 + h*DH + i + 32];
    } else {
        k0 = k1 = v0 = v1 = 0.f;
    }
    size_t base = ((size_t)bh*TTOTAL + s) * DH;
    out[OFF_K + base + i]      = k0;
    out[OFF_K + base + i + 32] = k1;
    out[OFF_V + base + i]      = v0;
    out[OFF_V + base + i + 32] = v1;
    if (s < ((tot + 63) & ~63)) {        // attention reads only < roundup(tot,64)
        g_kt[base + i]      = t32(k0);
        g_kt[base + i + 32] = t32(k1);
        g_vt[base + i]      = t32(v0);
        g_vt[base + i + 32] = t32(v1);
    }

    if (s < TNEW) {
        int t = s;
        float o0 = 0.f, o1 = 0.f;
        if (t < cnt) {
            int pos = pl + t;
            float sn, cs; rope_sc(pos, invf[i], sn, cs);
            size_t m = (size_t)(b*TNEW + t) * QKVN + h*DH;
            float x0 = g_qkv[m + i];
            float x1 = g_qkv[m + i + 32];
            o0 = t32(x0*cs - x1*sn) * 0.125f;
            o1 = t32(x1*cs + x0*sn) * 0.125f;
        }
        size_t qb = ((size_t)bh*TNEW + t) * DH;
        g_q[qb + i]      = o0;
        g_q[qb + i + 32] = o1;
    }
}

// ---------------------------------------------------------------------------
// Kernel 4: flash attention, tf32 mma. SINGLE K buffer + single V buffer:
// K(kb+1) issued after the post-S-mma barrier (hidden behind softmax+PV),
// V(kb) issued at iter start (hidden behind S-mma). smem = 52.2KB -> 4 CTAs.
// ---------------------------------------------------------------------------
#define AT 68
#define KVTILE (64*AT)

__global__ __launch_bounds__(128, 4) void k_attn()
{
    extern __shared__ float sm[];
    float* Ks = sm;
    float* Vs = sm + KVTILE;
    float (*Ps)[AT] = (float(*)[AT])(sm + 2*KVTILE);   // Q staging, then P

    int bh = blockIdx.x;
    int b = bh >> 4;
    int qb = blockIdx.y << 6;
    if (qb >= g_counts[b]) return;

    int tid = threadIdx.x;
    int warp = tid >> 5, lane = tid & 31;
    int r0 = lane >> 2, c0 = lane & 3;

    int tot = g_totals[b];
    int nkb = (tot + 63) >> 6;
    const float* kbase = g_kt + (size_t)bh*TTOTAL*DH;
    const float* vbase = g_vt + (size_t)bh*TTOTAL*DH;

    int prow = tid >> 4;
    int pcol = (tid & 15) * 4;

    // prefetch K tile 0
    #pragma unroll
    for (int j = 0; j < 8; j++) {
        int row = j*8 + prow;
        cpa16(&Ks[row*AT + pcol], &kbase[(size_t)row*DH + pcol]);
    }
    cpa_commit();

    // stage Q (already tf32+scaled) into Ps
    {
        const float* qp = g_q + ((size_t)bh*TNEW + qb) * DH;
        #pragma unroll
        for (int j = 0; j < 8; j++) {
            int id = j*128 + tid;
            int row = id >> 4;
            int c = (id & 15) * 4;
            *(float4*)&Ps[row][c] = *(const float4*)&qp[(size_t)row*DH + c];
        }
    }
    __syncthreads();

    unsigned qa[8][4];
    int qr = warp*16 + r0;
    #pragma unroll
    for (int ks = 0; ks < 8; ks++) {
        qa[ks][0] = U(Ps[qr  ][ks*8 + c0]);
        qa[ks][1] = U(Ps[qr+8][ks*8 + c0]);
        qa[ks][2] = U(Ps[qr  ][ks*8 + 4 + c0]);
        qa[ks][3] = U(Ps[qr+8][ks*8 + 4 + c0]);
    }

    float oacc[8][4];
    #pragma unroll
    for (int nt = 0; nt < 8; nt++)
        #pragma unroll
        for (int r = 0; r < 4; r++) oacc[nt][r] = 0.f;
    float mrow0 = -1e30f, mrow1 = -1e30f, lrow0 = 0.f, lrow1 = 0.f;

    for (int kb = 0; kb < nkb; kb++) {
        cpa_wait0();          // K(kb) resident (V from prev iter already consumed)
        __syncthreads();      // (1) prev PV reads of Vs/Ps done

        // issue V(kb): consumed after softmax, hidden behind S-mma
        {
            const float* vg = vbase + (size_t)kb*64*DH;
            #pragma unroll
            for (int j = 0; j < 8; j++) {
                int row = j*8 + prow;
                cpa16(&Vs[row*AT + pcol], &vg[(size_t)row*DH + pcol]);
            }
            cpa_commit();
        }

        // S = Q K^T
        float sacc[8][4];
        #pragma unroll
        for (int nt = 0; nt < 8; nt++)
            #pragma unroll
            for (int r = 0; r < 4; r++) sacc[nt][r] = 0.f;
        #pragma unroll
        for (int ks = 0; ks < 8; ks++) {
            #pragma unroll
            for (int nt = 0; nt < 8; nt++) {
                unsigned bb[2];
                bb[0] = U(Ks[(nt*8 + r0)*AT + ks*8 + c0]);
                bb[1] = U(Ks[(nt*8 + r0)*AT + ks*8 + 4 + c0]);
                mma8(sacc[nt], qa[ks], bb);
            }
        }
        __syncthreads();      // (2) all warps done reading Ks

        // issue K(kb+1) into the (now free) single K buffer:
        // hidden behind softmax + PV of this iteration
        bool havek = (kb + 1 < nkb);
        if (havek) {
            const float* kg = kbase + (size_t)(kb+1)*64*DH;
            #pragma unroll
            for (int j = 0; j < 8; j++) {
                int row = j*8 + prow;
                cpa16(&Ks[row*AT + pcol], &kg[(size_t)row*DH + pcol]);
            }
            cpa_commit();
        }

        // mask only on the final tile
        if (kb == nkb - 1) {
            #pragma unroll
            for (int nt = 0; nt < 8; nt++) {
                int col = kb*64 + nt*8 + 2*c0;
                if (col     >= tot) { sacc[nt][0] = -1e30f; sacc[nt][2] = -1e30f; }
                if (col + 1 >= tot) { sacc[nt][1] = -1e30f; sacc[nt][3] = -1e30f; }
            }
        }

        float ml0 = -1e30f, ml1 = -1e30f;
        #pragma unroll
        for (int nt = 0; nt < 8; nt++) {
            ml0 = fmaxf(ml0, fmaxf(sacc[nt][0], sacc[nt][1]));
            ml1 = fmaxf(ml1, fmaxf(sacc[nt][2], sacc[nt][3]));
        }
        ml0 = fmaxf(ml0, __shfl_xor_sync(0xffffffffu, ml0, 1));
        ml0 = fmaxf(ml0, __shfl_xor_sync(0xffffffffu, ml0, 2));
        ml1 = fmaxf(ml1, __shfl_xor_sync(0xffffffffu, ml1, 1));
        ml1 = fmaxf(ml1, __shfl_xor_sync(0xffffffffu, ml1, 2));

        float mn0 = fmaxf(mrow0, ml0), mn1 = fmaxf(mrow1, ml1);
        float e0 = __expf(mrow0 - mn0), e1 = __expf(mrow1 - mn1);
        mrow0 = mn0; mrow1 = mn1;

        float ls0 = 0.f, ls1 = 0.f;
        #pragma unroll
        for (int nt = 0; nt < 8; nt++) {
            float p0 = __expf(sacc[nt][0] - mn0);
            float p1 = __expf(sacc[nt][1] - mn0);
            float p2 = __expf(sacc[nt][2] - mn1);
            float p3 = __expf(sacc[nt][3] - mn1);
            ls0 += p0 + p1; ls1 += p2 + p3;
            float2 w0 = { t32(p0), t32(p1) };
            float2 w1 = { t32(p2), t32(p3) };
            *(float2*)&Ps[warp*16 + r0    ][nt*8 + 2*c0] = w0;
            *(float2*)&Ps[warp*16 + r0 + 8][nt*8 + 2*c0] = w1;
            oacc[nt][0] *= e0; oacc[nt][1] *= e0;
            oacc[nt][2] *= e1; oacc[nt][3] *= e1;
        }
        ls0 += __shfl_xor_sync(0xffffffffu, ls0, 1);
        ls0 += __shfl_xor_sync(0xffffffffu, ls0, 2);
        ls1 += __shfl_xor_sync(0xffffffffu, ls1, 1);
        ls1 += __shfl_xor_sync(0xffffffffu, ls1, 2);
        lrow0 = lrow0*e0 + ls0;
        lrow1 = lrow1*e1 + ls1;

        // V(kb) ready (keep K(kb+1) in flight when present)
        if (havek) cpa_wait1(); else cpa_wait0();
        __syncthreads();      // (3) Ps writes visible + Vs ready

        // O += P V
        #pragma unroll
        for (int ks = 0; ks < 8; ks++) {
            unsigned pa[4];
            pa[0] = U(Ps[warp*16 + r0    ][ks*8 + c0]);
            pa[1] = U(Ps[warp*16 + r0 + 8][ks*8 + c0]);
            pa[2] = U(Ps[warp*16 + r0    ][ks*8 + 4 + c0]);
            pa[3] = U(Ps[warp*16 + r0 + 8][ks*8 + 4 + c0]);
            #pragma unroll
            for (int nt = 0; nt < 8; nt++) {
                unsigned bb[2];
                bb[0] = U(Vs[(ks*8 + c0    )*AT + nt*8 + r0]);
                bb[1] = U(Vs[(ks*8 + 4 + c0)*AT + nt*8 + r0]);
                mma8(oacc[nt], pa, bb);
            }
        }
    }

    // finalize: tf32 values into g_ctx (k_gemm_out loads raw)
    float inv0 = 1.f / lrow0, inv1 = 1.f / lrow1;
    float* op = g_ctx + ((size_t)b*TNEW + qb + warp*16) * DMODEL + (bh & 15)*DH;
    #pragma unroll
    for (int nt = 0; nt < 8; nt++) {
        int col = nt*8 + 2*c0;
        float2 v0 = { t32(oacc[nt][0]*inv0), t32(oacc[nt][1]*inv0) };
        float2 v1 = { t32(oacc[nt][2]*inv1), t32(oacc[nt][3]*inv1) };
        *(float2*)&op[(size_t)r0*DMODEL + col]       = v0;
        *(float2*)&op[(size_t)(r0+8)*DMODEL + col]   = v1;
    }
}

// ---------------------------------------------------------------------------
// Kernel 5: output projection (pipelined, zero-cvt) + valid-token mask.
// ---------------------------------------------------------------------------
__global__ __launch_bounds__(256) void k_gemm_out(
    const float* __restrict__ bo, float* __restrict__ out)
{
    extern __shared__ float smem_g[];
    float* sA = smem_g;
    float* sB = smem_g + 2*GSTAGE;

    int bm = blockIdx.y * 128;
    int bn = blockIdx.x * 128;
    int tid = threadIdx.x;

    if ((bm & 511) >= g_counts[bm >> 9]) {
        float4 z = {0.f, 0.f, 0.f, 0.f};
        #pragma unroll
        for (int j = 0; j < 16; j++) {
            int id = j*256 + tid;
            int row = id >> 5;
            int col = (id & 31) * 4;
            *(float4*)&out[(size_t)(bm + row)*DMODEL + bn + col] = z;
        }
        return;
    }

    int warp = tid >> 5, lane = tid & 31;
    int wm = warp >> 1, wn = warp & 1;
    int r0 = lane >> 2, c0 = lane & 3;

    float acc[2][8][4];
    #pragma unroll
    for (int mt = 0; mt < 2; mt++)
        #pragma unroll
        for (int nt = 0; nt < 8; nt++)
            #pragma unroll
            for (int r = 0; r < 4; r++) acc[mt][nt][r] = 0.f;

    gemm_pipe(g_ctx + (size_t)bm*DMODEL,
              g_wt + (size_t)3*WSZ + (size_t)bn*DMODEL,
              sA, sB, tid, acc);

    #pragma unroll
    for (int mt = 0; mt < 2; mt++) {
        int row = bm + wm*32 + mt*16 + r0;
        int bb0 = (row)     >> 9, tt0 = (row)     & 511;
        int bb1 = (row + 8) >> 9, tt1 = (row + 8) & 511;
        float m0 = (tt0 < g_counts[bb0]) ? 1.f : 0.f;
        float m1 = (tt1 < g_counts[bb1]) ? 1.f : 0.f;
        #pragma unroll
        for (int nt = 0; nt < 8; nt++) {
            int col = bn + wn*64 + nt*8 + 2*c0;
            float bx = bo[col], by = bo[col+1];
            float2 v0 = { (acc[mt][nt][0] + bx)*m0, (acc[mt][nt][1] + by)*m0 };
            float2 v1 = { (acc[mt][nt][2] + bx)*m1, (acc[mt][nt][3] + by)*m1 };
            *(float2*)&out[(size_t)row*DMODEL + col]     = v0;
            *(float2*)&out[(size_t)(row+8)*DMODEL + col] = v1;
        }
    }
}

// ---------------------------------------------------------------------------
extern "C" void kernel_launch(void* const* d_in, const int* in_sizes, int n_in,
                              void* d_out, int out_size)
{
    const float* x     = (const float*)d_in[0];
    const float* invf  = (const float*)d_in[1];
    const float* pastk = (const float*)d_in[2];
    const float* pastv = (const float*)d_in[3];
    const float* Wq    = (const float*)d_in[4];
    const float* bq    = (const float*)d_in[5];
    const float* Wk    = (const float*)d_in[6];
    const float* bk    = (const float*)d_in[7];
    const float* Wv    = (const float*)d_in[8];
    const float* bv    = (const float*)d_in[9];
    const float* Wo    = (const float*)d_in[10];
    const float* bo    = (const float*)d_in[11];
    const int* past_len = (const int*)d_in[13];
    const unsigned char* vmask = (const unsigned char*)d_in[14];
    float* out = (float*)d_out;

    int gsmem = 4*GSTAGE*4;  // 73728 B
    cudaFuncSetAttribute(k_gemm_qkv, cudaFuncAttributeMaxDynamicSharedMemorySize, gsmem);
    cudaFuncSetAttribute(k_gemm_out, cudaFuncAttributeMaxDynamicSharedMemorySize, gsmem);

    k_setup<<<B_, 32>>>(vmask, past_len, out + OFF_LEN);
    k_cvt<<<(MROWS*DMODEL + 4*WSZ)/4/256, 256>>>(x, Wq, Wk, Wv, Wo);
    k_gemm_qkv<<<dim3(QKVN/128, MROWS/128), 256, gsmem>>>(bq, bk, bv);
    k_prep<<<dim3(TTOTAL*32/256, B_*H_), 256>>>(pastk, pastv, invf, past_len, out);

    int smem = (2*KVTILE + 64*AT) * 4;   // 52224 B -> 4 CTAs/SM
    cudaFuncSetAttribute(k_attn, cudaFuncAttributeMaxDynamicSharedMemorySize, smem);
    k_attn<<<dim3(B_*H_, TNEW/64), 128, smem>>>();

    k_gemm_out<<<dim3(DMODEL/128, MROWS/128), 256, gsmem>>>(bo, out);
}

// round 13
// speedup vs baseline: 1.0261x; 1.0261x over previous
#include <cuda_runtime.h>
#include <math.h>

#define B_      8
#define TNEW    512
#define DMODEL  1024
#define H_      16
#define DH      64
#define CACHED  2048
#define TTOTAL  2560
#define MROWS   (B_*TNEW)      // 4096
#define QKVN    3072

#define OFF_K   (MROWS*DMODEL)               // 4194304
#define OFF_V   (OFF_K + B_*H_*TTOTAL*DH)    // 25165824
#define OFF_LEN (OFF_V + B_*H_*TTOTAL*DH)    // 46137344

#define WSZ     (DMODEL*DMODEL)              // 1048576

// Scratch (allocation-free rule: __device__ globals)
__device__ float g_qkv[MROWS*QKVN];        // raw q|k|v projections [4096][3072]
__device__ float g_q  [B_*H_*TNEW*DH];     // roped q (tf32, pre-scaled by 1/8)
__device__ float g_kt [B_*H_*TTOTAL*DH];   // tf32 copy of k_total
__device__ float g_vt [B_*H_*TTOTAL*DH];   // tf32 copy of v_total
__device__ float g_ctx[MROWS*DMODEL];      // attention context (tf32 values)
__device__ float g_xt [MROWS*DMODEL];      // tf32 copy of x_new
__device__ float g_wt [4*WSZ];             // tf32 copies of Wq|Wk|Wv|Wo
__device__ int   g_counts[B_];
__device__ int   g_totals[B_];

// ---------------------------------------------------------------------------
// tf32 / cp.async helpers
// ---------------------------------------------------------------------------
__device__ __forceinline__ float t32(float f) {
    unsigned u;
    asm("cvt.rna.tf32.f32 %0, %1;" : "=r"(u) : "f"(f));
    return __uint_as_float(u);
}
__device__ __forceinline__ unsigned U(float f) { return __float_as_uint(f); }

__device__ __forceinline__ void mma8(float* c, const unsigned* a, const unsigned* b) {
    asm volatile(
        "mma.sync.aligned.m16n8k8.row.col.f32.tf32.tf32.f32 "
        "{%0,%1,%2,%3},{%4,%5,%6,%7},{%8,%9},{%0,%1,%2,%3};"
        : "+f"(c[0]), "+f"(c[1]), "+f"(c[2]), "+f"(c[3])
        : "r"(a[0]), "r"(a[1]), "r"(a[2]), "r"(a[3]), "r"(b[0]), "r"(b[1]));
}

__device__ __forceinline__ void cpa16(float* smem, const float* g) {
    unsigned s = (unsigned)__cvta_generic_to_shared(smem);
    asm volatile("cp.async.cg.shared.global [%0], [%1], 16;" :: "r"(s), "l"(g));
}
__device__ __forceinline__ void cpa_commit() { asm volatile("cp.async.commit_group;"); }
__device__ __forceinline__ void cpa_wait1()  { asm volatile("cp.async.wait_group 1;"); }
__device__ __forceinline__ void cpa_wait0()  { asm volatile("cp.async.wait_group 0;"); }

// ---------------------------------------------------------------------------
// Kernel 0: one-time tf32 pre-conversion of X and W matrices
// ---------------------------------------------------------------------------
__global__ __launch_bounds__(256) void k_cvt(
    const float* __restrict__ X,
    const float* __restrict__ Wq, const float* __restrict__ Wk,
    const float* __restrict__ Wv, const float* __restrict__ Wo)
{
    int idx = blockIdx.x * 256 + threadIdx.x;     // float4 index
    const int XQ = MROWS*DMODEL/4;
    float4 v; float4* dst;
    if (idx < XQ) {
        v = ((const float4*)X)[idx];
        dst = (float4*)g_xt + idx;
    } else {
        int r = idx - XQ;
        int w = r / (WSZ/4);
        int o = r % (WSZ/4);
        const float* src = (w == 0) ? Wq : (w == 1) ? Wk : (w == 2) ? Wv : Wo;
        v = ((const float4*)src)[o];
        dst = (float4*)(g_wt + (size_t)w*WSZ) + o;
    }
    float4 ov = { t32(v.x), t32(v.y), t32(v.z), t32(v.w) };
    *dst = ov;
}

// ---------------------------------------------------------------------------
// Kernel 1: derive new_counts from valid_new_mask (dtype-probed), totals
// ---------------------------------------------------------------------------
__global__ void k_setup(const unsigned char* __restrict__ mask,
                        const int* __restrict__ past_len,
                        float* __restrict__ out_len)
{
    int b = blockIdx.x;
    int lane = threadIdx.x;
    bool bytemode = (mask[7*TNEW + 1] != 0);
    int cnt = 0;
    for (int t = lane; t < TNEW; t += 32) {
        int nz;
        if (bytemode) nz = (mask[b*TNEW + t] != 0);
        else          nz = (((const int*)mask)[b*TNEW + t] != 0);
        cnt += nz;
    }
    #pragma unroll
    for (int o = 16; o; o >>= 1) cnt += __shfl_xor_sync(0xffffffffu, cnt, o);
    if (lane == 0) {
        g_counts[b] = cnt;
        int tot = past_len[b] + cnt;
        g_totals[b] = tot;
        out_len[b] = (float)tot;
    }
}

// ---------------------------------------------------------------------------
// Accurate RoPE angles (fp64 range reduction, fp32 sincos)
// ---------------------------------------------------------------------------
__device__ __forceinline__ void rope_sc(int pos, float fi, float& sn, float& cs)
{
    double f = (double)pos * (double)fi;
    double k = floor(f * 0.15915494309189535);
    float fr = (float)(f - k * 6.283185307179586);
    sincosf(fr, &sn, &cs);
}

// ---------------------------------------------------------------------------
// Shared GEMM body: 128x128 tile, ktile 32, 2-stage cp.async pipeline.
// Inputs are PRE-CONVERTED tf32 -> zero cvt in the loop, raw fragment loads.
// ---------------------------------------------------------------------------
#define GST 36
#define GSTAGE (128*GST)

__device__ __forceinline__ void gemm_pipe(
    const float* __restrict__ Ag, const float* __restrict__ Bg,
    float* sA, float* sB, int tid, float acc[2][8][4])
{
    int warp = tid >> 5, lane = tid & 31;
    int wm = warp >> 1, wn = warp & 1;
    int r0 = lane >> 2, c0 = lane & 3;
    int lrow = tid >> 3;
    int lcol = (tid & 7) * 4;

    #pragma unroll
    for (int it = 0; it < 4; it++) {
        int row = it*32 + lrow;
        cpa16(&sA[row*GST + lcol], &Ag[(size_t)row*DMODEL + lcol]);
        cpa16(&sB[row*GST + lcol], &Bg[(size_t)row*DMODEL + lcol]);
    }
    cpa_commit();

    for (int kt = 0; kt < 32; kt++) {
        int st = (kt & 1) * GSTAGE;
        if (kt + 1 < 32) {
            int ns = ((kt + 1) & 1) * GSTAGE;
            int k0 = (kt + 1) * 32;
            #pragma unroll
            for (int it = 0; it < 4; it++) {
                int row = it*32 + lrow;
                cpa16(&sA[ns + row*GST + lcol], &Ag[(size_t)row*DMODEL + k0 + lcol]);
                cpa16(&sB[ns + row*GST + lcol], &Bg[(size_t)row*DMODEL + k0 + lcol]);
            }
            cpa_commit();
            cpa_wait1();
        } else {
            cpa_wait0();
        }
        __syncthreads();

        #pragma unroll
        for (int ks = 0; ks < 4; ks++) {
            int kk = ks*8;
            unsigned a[2][4], b[8][2];
            #pragma unroll
            for (int mt = 0; mt < 2; mt++) {
                int mr = wm*32 + mt*16 + r0;
                a[mt][0] = U(sA[st + (mr    )*GST + kk + c0]);
                a[mt][1] = U(sA[st + (mr + 8)*GST + kk + c0]);
                a[mt][2] = U(sA[st + (mr    )*GST + kk + 4 + c0]);
                a[mt][3] = U(sA[st + (mr + 8)*GST + kk + 4 + c0]);
            }
            #pragma unroll
            for (int nt = 0; nt < 8; nt++) {
                int nr = wn*64 + nt*8 + r0;
                b[nt][0] = U(sB[st + nr*GST + kk + c0]);
                b[nt][1] = U(sB[st + nr*GST + kk + 4 + c0]);
            }
            #pragma unroll
            for (int mt = 0; mt < 2; mt++)
                #pragma unroll
                for (int nt = 0; nt < 8; nt++)
                    mma8(acc[mt][nt], a[mt], b[nt]);
        }
        __syncthreads();
    }
}

// ---------------------------------------------------------------------------
// Kernel 2: QKV projection (pipelined, zero-cvt). Dead-row blocks exit.
// ---------------------------------------------------------------------------
__global__ __launch_bounds__(256) void k_gemm_qkv(
    const float* __restrict__ bq, const float* __restrict__ bk, const float* __restrict__ bv)
{
    extern __shared__ float smem_g[];
    float* sA = smem_g;
    float* sB = smem_g + 2*GSTAGE;

    int bm = blockIdx.y * 128;
    if ((bm & 511) >= g_counts[bm >> 9]) return;

    int bn = blockIdx.x * 128;
    int seg = bn >> 10;
    const float* bias = (seg == 0) ? bq : ((seg == 1) ? bk : bv);
    int nl = bn & 1023;
    int tid = threadIdx.x;
    int warp = tid >> 5, lane = tid & 31;
    int wm = warp >> 1, wn = warp & 1;
    int r0 = lane >> 2, c0 = lane & 3;

    float acc[2][8][4];
    #pragma unroll
    for (int mt = 0; mt < 2; mt++)
        #pragma unroll
        for (int nt = 0; nt < 8; nt++)
            #pragma unroll
            for (int r = 0; r < 4; r++) acc[mt][nt][r] = 0.f;

    gemm_pipe(g_xt + (size_t)bm*DMODEL,
              g_wt + (size_t)seg*WSZ + (size_t)nl*DMODEL,
              sA, sB, tid, acc);

    #pragma unroll
    for (int mt = 0; mt < 2; mt++) {
        #pragma unroll
        for (int nt = 0; nt < 8; nt++) {
            int row = bm + wm*32 + mt*16 + r0;
            int col = bn + wn*64 + nt*8 + 2*c0;
            float bx = bias[col & 1023], by = bias[(col+1) & 1023];
            float2 v0 = { acc[mt][nt][0] + bx, acc[mt][nt][1] + by };
            float2 v1 = { acc[mt][nt][2] + bx, acc[mt][nt][3] + by };
            *(float2*)&g_qkv[(size_t)row*QKVN + col]     = v0;
            *(float2*)&g_qkv[(size_t)(row+8)*QKVN + col] = v1;
        }
    }
}

// ---------------------------------------------------------------------------
// Kernel 3 (fused): assemble k_total/v_total + RoPE on q.
// tf32 mirrors written only up to roundup(tot,64) (attention never reads past).
// ---------------------------------------------------------------------------
__global__ __launch_bounds__(256) void k_prep(
    const float* __restrict__ pastk, const float* __restrict__ pastv,
    const float* __restrict__ invf, const int* __restrict__ past_len,
    float* __restrict__ out)
{
    int bh = blockIdx.y; int b = bh >> 4; int h = bh & 15;
    int gid = blockIdx.x * 256 + threadIdx.x;
    int i = gid & 31; int s = gid >> 5;
    int pl = past_len[b]; int tot = g_totals[b]; int cnt = g_counts[b];
    float k0, k1, v0, v1;
    if (s < pl) {
        size_t base = ((size_t)bh*CACHED + s) * DH;
        k0 = pastk[base + i]; k1 = pastk[base + i + 32];
        v0 = pastv[base + i]; v1 = pastv[base + i + 32];
    } else if (s < tot) {
        int t = s - pl;
        size_t m = (size_t)(b*TNEW + t) * QKVN;
        float sn, cs; rope_sc(s, invf[i], sn, cs);
        float x0 = g_qkv[m + 1024 + h*DH + i];
        float x1 = g_qkv[m + 1024 + h*DH + i + 32];
        k0 = x0*cs - x1*sn;
        k1 = x1*cs + x0*sn;
        v0 = g_qkv[m + 2048 + h*DH + i];
        v1 = g_qkv[m + 2048 + h*DH + i + 32];
    } else {
        k0 = k1 = v0 = v1 = 0.f;
    }
    size_t base = ((size_t)bh*TTOTAL + s) * DH;
    out[OFF_K + base + i]      = k0;
    out[OFF_K + base + i + 32] = k1;
    out[OFF_V + base + i]      = v0;
    out[OFF_V + base + i + 32] = v1;
    if (s < ((tot + 63) & ~63)) {        // attention reads only < roundup(tot,64)
        g_kt[base + i]      = t32(k0);
        g_kt[base + i + 32] = t32(k1);
        g_vt[base + i]      = t32(v0);
        g_vt[base + i + 32] = t32(v1);
    }

    if (s < TNEW) {
        int t = s;
        float o0 = 0.f, o1 = 0.f;
        if (t < cnt) {
            int pos = pl + t;
            float sn, cs; rope_sc(pos, invf[i], sn, cs);
            size_t m = (size_t)(b*TNEW + t) * QKVN + h*DH;
            float x0 = g_qkv[m + i];
            float x1 = g_qkv[m + i + 32];
            o0 = t32(x0*cs - x1*sn) * 0.125f;
            o1 = t32(x1*cs + x0*sn) * 0.125f;
        }
        size_t qb = ((size_t)bh*TNEW + t) * DH;
        g_q[qb + i]      = o0;
        g_q[qb + i + 32] = o1;
    }
}

// ---------------------------------------------------------------------------
// Kernel 4: flash attention (R11 geometry: K double-buffered cp.async,
// V single-buffered, Ps in smem, 3 CTAs/SM). Scale folded into q;
// column masking applied only on the final k-tile.
// ---------------------------------------------------------------------------
#define AT 68
#define KVTILE (64*AT)

__global__ __launch_bounds__(128, 3) void k_attn()
{
    extern __shared__ float sm[];
    float* Kb[2] = { sm, sm + KVTILE };
    float* Vs = sm + 2*KVTILE;
    float (*Ps)[AT] = (float(*)[AT])(sm + 3*KVTILE);

    int bh = blockIdx.x;
    int b = bh >> 4;
    int qb = blockIdx.y << 6;
    if (qb >= g_counts[b]) return;

    int tid = threadIdx.x;
    int warp = tid >> 5, lane = tid & 31;
    int r0 = lane >> 2, c0 = lane & 3;

    int tot = g_totals[b];
    int nkb = (tot + 63) >> 6;
    const float* kbase = g_kt + (size_t)bh*TTOTAL*DH;
    const float* vbase = g_vt + (size_t)bh*TTOTAL*DH;

    int prow = tid >> 4;
    int pcol = (tid & 15) * 4;

    #pragma unroll
    for (int j = 0; j < 8; j++) {
        int row = j*8 + prow;
        cpa16(&Kb[0][row*AT + pcol], &kbase[(size_t)row*DH + pcol]);
    }
    cpa_commit();

    {
        const float* qp = g_q + ((size_t)bh*TNEW + qb) * DH;
        #pragma unroll
        for (int j = 0; j < 8; j++) {
            int id = j*128 + tid;
            int row = id >> 4;
            int c = (id & 15) * 4;
            *(float4*)&Ps[row][c] = *(const float4*)&qp[(size_t)row*DH + c];
        }
    }
    __syncthreads();

    unsigned qa[8][4];
    int qr = warp*16 + r0;
    #pragma unroll
    for (int ks = 0; ks < 8; ks++) {
        qa[ks][0] = U(Ps[qr  ][ks*8 + c0]);
        qa[ks][1] = U(Ps[qr+8][ks*8 + c0]);
        qa[ks][2] = U(Ps[qr  ][ks*8 + 4 + c0]);
        qa[ks][3] = U(Ps[qr+8][ks*8 + 4 + c0]);
    }

    float oacc[8][4];
    #pragma unroll
    for (int nt = 0; nt < 8; nt++)
        #pragma unroll
        for (int r = 0; r < 4; r++) oacc[nt][r] = 0.f;
    float mrow0 = -1e30f, mrow1 = -1e30f, lrow0 = 0.f, lrow1 = 0.f;

    for (int kb = 0; kb < nkb; kb++) {
        cpa_wait0();
        __syncthreads();

        {
            const float* vg = vbase + (size_t)kb*64*DH;
            #pragma unroll
            for (int j = 0; j < 8; j++) {
                int row = j*8 + prow;
                cpa16(&Vs[row*AT + pcol], &vg[(size_t)row*DH + pcol]);
            }
            cpa_commit();
        }
        bool havek = (kb + 1 < nkb);
        if (havek) {
            int nb = (kb + 1) & 1;
            const float* kg = kbase + (size_t)(kb+1)*64*DH;
            #pragma unroll
            for (int j = 0; j < 8; j++) {
                int row = j*8 + prow;
                cpa16(&Kb[nb][row*AT + pcol], &kg[(size_t)row*DH + pcol]);
            }
            cpa_commit();
        }

        const float* Ks = Kb[kb & 1];

        float sacc[8][4];
        #pragma unroll
        for (int nt = 0; nt < 8; nt++)
            #pragma unroll
            for (int r = 0; r < 4; r++) sacc[nt][r] = 0.f;
        #pragma unroll
        for (int ks = 0; ks < 8; ks++) {
            #pragma unroll
            for (int nt = 0; nt < 8; nt++) {
                unsigned bb[2];
                bb[0] = U(Ks[(nt*8 + r0)*AT + ks*8 + c0]);
                bb[1] = U(Ks[(nt*8 + r0)*AT + ks*8 + 4 + c0]);
                mma8(sacc[nt], qa[ks], bb);
            }
        }

        if (kb == nkb - 1) {
            #pragma unroll
            for (int nt = 0; nt < 8; nt++) {
                int col = kb*64 + nt*8 + 2*c0;
                if (col     >= tot) { sacc[nt][0] = -1e30f; sacc[nt][2] = -1e30f; }
                if (col + 1 >= tot) { sacc[nt][1] = -1e30f; sacc[nt][3] = -1e30f; }
            }
        }

        float ml0 = -1e30f, ml1 = -1e30f;
        #pragma unroll
        for (int nt = 0; nt < 8; nt++) {
            ml0 = fmaxf(ml0, fmaxf(sacc[nt][0], sacc[nt][1]));
            ml1 = fmaxf(ml1, fmaxf(sacc[nt][2], sacc[nt][3]));
        }
        ml0 = fmaxf(ml0, __shfl_xor_sync(0xffffffffu, ml0, 1));
        ml0 = fmaxf(ml0, __shfl_xor_sync(0xffffffffu, ml0, 2));
        ml1 = fmaxf(ml1, __shfl_xor_sync(0xffffffffu, ml1, 1));
        ml1 = fmaxf(ml1, __shfl_xor_sync(0xffffffffu, ml1, 2));

        float mn0 = fmaxf(mrow0, ml0), mn1 = fmaxf(mrow1, ml1);
        float e0 = __expf(mrow0 - mn0), e1 = __expf(mrow1 - mn1);
        mrow0 = mn0; mrow1 = mn1;

        float ls0 = 0.f, ls1 = 0.f;
        #pragma unroll
        for (int nt = 0; nt < 8; nt++) {
            float p0 = __expf(sacc[nt][0] - mn0);
            float p1 = __expf(sacc[nt][1] - mn0);
            float p2 = __expf(sacc[nt][2] - mn1);
            float p3 = __expf(sacc[nt][3] - mn1);
            ls0 += p0 + p1; ls1 += p2 + p3;
            float2 w0 = { t32(p0), t32(p1) };
            float2 w1 = { t32(p2), t32(p3) };
            *(float2*)&Ps[warp*16 + r0    ][nt*8 + 2*c0] = w0;
            *(float2*)&Ps[warp*16 + r0 + 8][nt*8 + 2*c0] = w1;
            oacc[nt][0] *= e0; oacc[nt][1] *= e0;
            oacc[nt][2] *= e1; oacc[nt][3] *= e1;
        }
        ls0 += __shfl_xor_sync(0xffffffffu, ls0, 1);
        ls0 += __shfl_xor_sync(0xffffffffu, ls0, 2);
        ls1 += __shfl_xor_sync(0xffffffffu, ls1, 1);
        ls1 += __shfl_xor_sync(0xffffffffu, ls1, 2);
        lrow0 = lrow0*e0 + ls0;
        lrow1 = lrow1*e1 + ls1;

        if (havek) cpa_wait1(); else cpa_wait0();
        __syncthreads();

        #pragma unroll
        for (int ks = 0; ks < 8; ks++) {
            unsigned pa[4];
            pa[0] = U(Ps[warp*16 + r0    ][ks*8 + c0]);
            pa[1] = U(Ps[warp*16 + r0 + 8][ks*8 + c0]);
            pa[2] = U(Ps[warp*16 + r0    ][ks*8 + 4 + c0]);
            pa[3] = U(Ps[warp*16 + r0 + 8][ks*8 + 4 + c0]);
            #pragma unroll
            for (int nt = 0; nt < 8; nt++) {
                unsigned bb[2];
                bb[0] = U(Vs[(ks*8 + c0    )*AT + nt*8 + r0]);
                bb[1] = U(Vs[(ks*8 + 4 + c0)*AT + nt*8 + r0]);
                mma8(oacc[nt], pa, bb);
            }
        }
    }

    // finalize: tf32 values into g_ctx (k_gemm_out loads raw)
    float inv0 = 1.f / lrow0, inv1 = 1.f / lrow1;
    float* op = g_ctx + ((size_t)b*TNEW + qb + warp*16) * DMODEL + (bh & 15)*DH;
    #pragma unroll
    for (int nt = 0; nt < 8; nt++) {
        int col = nt*8 + 2*c0;
        float2 v0 = { t32(oacc[nt][0]*inv0), t32(oacc[nt][1]*inv0) };
        float2 v1 = { t32(oacc[nt][2]*inv1), t32(oacc[nt][3]*inv1) };
        *(float2*)&op[(size_t)r0*DMODEL + col]       = v0;
        *(float2*)&op[(size_t)(r0+8)*DMODEL + col]   = v1;
    }
}

// ---------------------------------------------------------------------------
// Kernel 5: output projection (pipelined, zero-cvt) + valid-token mask.
// ---------------------------------------------------------------------------
__global__ __launch_bounds__(256) void k_gemm_out(
    const float* __restrict__ bo, float* __restrict__ out)
{
    extern __shared__ float smem_g[];
    float* sA = smem_g;
    float* sB = smem_g + 2*GSTAGE;

    int bm = blockIdx.y * 128;
    int bn = blockIdx.x * 128;
    int tid = threadIdx.x;

    if ((bm & 511) >= g_counts[bm >> 9]) {
        float4 z = {0.f, 0.f, 0.f, 0.f};
        #pragma unroll
        for (int j = 0; j < 16; j++) {
            int id = j*256 + tid;
            int row = id >> 5;
            int col = (id & 31) * 4;
            *(float4*)&out[(size_t)(bm + row)*DMODEL + bn + col] = z;
        }
        return;
    }

    int warp = tid >> 5, lane = tid & 31;
    int wm = warp >> 1, wn = warp & 1;
    int r0 = lane >> 2, c0 = lane & 3;

    float acc[2][8][4];
    #pragma unroll
    for (int mt = 0; mt < 2; mt++)
        #pragma unroll
        for (int nt = 0; nt < 8; nt++)
            #pragma unroll
            for (int r = 0; r < 4; r++) acc[mt][nt][r] = 0.f;

    gemm_pipe(g_ctx + (size_t)bm*DMODEL,
              g_wt + (size_t)3*WSZ + (size_t)bn*DMODEL,
              sA, sB, tid, acc);

    #pragma unroll
    for (int mt = 0; mt < 2; mt++) {
        int row = bm + wm*32 + mt*16 + r0;
        int bb0 = (row)     >> 9, tt0 = (row)     & 511;
        int bb1 = (row + 8) >> 9, tt1 = (row + 8) & 511;
        float m0 = (tt0 < g_counts[bb0]) ? 1.f : 0.f;
        float m1 = (tt1 < g_counts[bb1]) ? 1.f : 0.f;
        #pragma unroll
        for (int nt = 0; nt < 8; nt++) {
            int col = bn + wn*64 + nt*8 + 2*c0;
            float bx = bo[col], by = bo[col+1];
            float2 v0 = { (acc[mt][nt][0] + bx)*m0, (acc[mt][nt][1] + by)*m0 };
            float2 v1 = { (acc[mt][nt][2] + bx)*m1, (acc[mt][nt][3] + by)*m1 };
            *(float2*)&out[(size_t)row*DMODEL + col]     = v0;
            *(float2*)&out[(size_t)(row+8)*DMODEL + col] = v1;
        }
    }
}

// ---------------------------------------------------------------------------
extern "C" void kernel_launch(void* const* d_in, const int* in_sizes, int n_in,
                              void* d_out, int out_size)
{
    const float* x     = (const float*)d_in[0];
    const float* invf  = (const float*)d_in[1];
    const float* pastk = (const float*)d_in[2];
    const float* pastv = (const float*)d_in[3];
    const float* Wq    = (const float*)d_in[4];
    const float* bq    = (const float*)d_in[5];
    const float* Wk    = (const float*)d_in[6];
    const float* bk    = (const float*)d_in[7];
    const float* Wv    = (const float*)d_in[8];
    const float* bv    = (const float*)d_in[9];
    const float* Wo    = (const float*)d_in[10];
    const float* bo    = (const float*)d_in[11];
    const int* past_len = (const int*)d_in[13];
    const unsigned char* vmask = (const unsigned char*)d_in[14];
    float* out = (float*)d_out;

    int gsmem = 4*GSTAGE*4;  // 73728 B
    cudaFuncSetAttribute(k_gemm_qkv, cudaFuncAttributeMaxDynamicSharedMemorySize, gsmem);
    cudaFuncSetAttribute(k_gemm_out, cudaFuncAttributeMaxDynamicSharedMemorySize, gsmem);

    k_setup<<<B_, 32>>>(vmask, past_len, out + OFF_LEN);
    k_cvt<<<(MROWS*DMODEL + 4*WSZ)/4/256, 256>>>(x, Wq, Wk, Wv, Wo);
    k_gemm_qkv<<<dim3(QKVN/128, MROWS/128), 256, gsmem>>>(bq, bk, bv);
    k_prep<<<dim3(TTOTAL*32/256, B_*H_), 256>>>(pastk, pastv, invf, past_len, out);

    int smem = (3*KVTILE + 64*AT) * 4;   // 69632 -> 3 CTAs/SM
    cudaFuncSetAttribute(k_attn, cudaFuncAttributeMaxDynamicSharedMemorySize, smem);
    k_attn<<<dim3(B_*H_, TNEW/64), 128, smem>>>();

    k_gemm_out<<<dim3(DMODEL/128, MROWS/128), 256, gsmem>>>(bo, out);
}

// round 15
// speedup vs baseline: 1.0473x; 1.0206x over previous
#include <cuda_runtime.h>
#include <math.h>

#define B_      8
#define TNEW    512
#define DMODEL  1024
#define H_      16
#define DH      64
#define CACHED  2048
#define TTOTAL  2560
#define MROWS   (B_*TNEW)      // 4096
#define QKVN    3072

#define OFF_K   (MROWS*DMODEL)               // 4194304
#define OFF_V   (OFF_K + B_*H_*TTOTAL*DH)    // 25165824
#define OFF_LEN (OFF_V + B_*H_*TTOTAL*DH)    // 46137344

#define WSZ     (DMODEL*DMODEL)              // 1048576

// Scratch (allocation-free rule: __device__ globals)
__device__ float g_qkv[MROWS*QKVN];        // raw q|k|v projections [4096][3072]
__device__ float g_q  [B_*H_*TNEW*DH];     // roped q (tf32, pre-scaled by 1/8)
__device__ float g_kt [B_*H_*TTOTAL*DH];   // tf32 copy of k_total
__device__ float g_vt [B_*H_*TTOTAL*DH];   // tf32 copy of v_total
__device__ float g_ctx[MROWS*DMODEL];      // attention context (tf32 values)
__device__ float g_xt [MROWS*DMODEL];      // tf32 copy of x_new
__device__ float g_wt [4*WSZ];             // tf32 copies of Wq|Wk|Wv|Wo
__device__ int   g_counts[B_];
__device__ int   g_totals[B_];
__device__ int   g_work[B_*H_*(TNEW/64)];  // packed (bh<<3 | qblock) work items
__device__ int   g_nwork;
__device__ int   g_wctr;

// ---------------------------------------------------------------------------
// tf32 / cp.async helpers
// ---------------------------------------------------------------------------
__device__ __forceinline__ float t32(float f) {
    unsigned u;
    asm("cvt.rna.tf32.f32 %0, %1;" : "=r"(u) : "f"(f));
    return __uint_as_float(u);
}
__device__ __forceinline__ unsigned U(float f) { return __float_as_uint(f); }

__device__ __forceinline__ void mma8(float* c, const unsigned* a, const unsigned* b) {
    asm volatile(
        "mma.sync.aligned.m16n8k8.row.col.f32.tf32.tf32.f32 "
        "{%0,%1,%2,%3},{%4,%5,%6,%7},{%8,%9},{%0,%1,%2,%3};"
        : "+f"(c[0]), "+f"(c[1]), "+f"(c[2]), "+f"(c[3])
        : "r"(a[0]), "r"(a[1]), "r"(a[2]), "r"(a[3]), "r"(b[0]), "r"(b[1]));
}

__device__ __forceinline__ void cpa16(float* smem, const float* g) {
    unsigned s = (unsigned)__cvta_generic_to_shared(smem);
    asm volatile("cp.async.cg.shared.global [%0], [%1], 16;" :: "r"(s), "l"(g));
}
__device__ __forceinline__ void cpa_commit() { asm volatile("cp.async.commit_group;"); }
__device__ __forceinline__ void cpa_wait1()  { asm volatile("cp.async.wait_group 1;"); }
__device__ __forceinline__ void cpa_wait0()  { asm volatile("cp.async.wait_group 0;"); }

// ---------------------------------------------------------------------------
// Kernel 0: one-time tf32 pre-conversion of X and W matrices
// ---------------------------------------------------------------------------
__global__ __launch_bounds__(256) void k_cvt(
    const float* __restrict__ X,
    const float* __restrict__ Wq, const float* __restrict__ Wk,
    const float* __restrict__ Wv, const float* __restrict__ Wo)
{
    int idx = blockIdx.x * 256 + threadIdx.x;     // float4 index
    const int XQ = MROWS*DMODEL/4;
    float4 v; float4* dst;
    if (idx < XQ) {
        v = ((const float4*)X)[idx];
        dst = (float4*)g_xt + idx;
    } else {
        int r = idx - XQ;
        int w = r / (WSZ/4);
        int o = r % (WSZ/4);
        const float* src = (w == 0) ? Wq : (w == 1) ? Wk : (w == 2) ? Wv : Wo;
        v = ((const float4*)src)[o];
        dst = (float4*)(g_wt + (size_t)w*WSZ) + o;
    }
    float4 ov = { t32(v.x), t32(v.y), t32(v.z), t32(v.w) };
    *dst = ov;
}

// ---------------------------------------------------------------------------
// Kernel 1: derive new_counts from valid_new_mask (dtype-probed), totals
// ---------------------------------------------------------------------------
__global__ void k_setup(const unsigned char* __restrict__ mask,
                        const int* __restrict__ past_len,
                        float* __restrict__ out_len)
{
    int b = blockIdx.x;
    int lane = threadIdx.x;
    bool bytemode = (mask[7*TNEW + 1] != 0);
    int cnt = 0;
    for (int t = lane; t < TNEW; t += 32) {
        int nz;
        if (bytemode) nz = (mask[b*TNEW + t] != 0);
        else          nz = (((const int*)mask)[b*TNEW + t] != 0);
        cnt += nz;
    }
    #pragma unroll
    for (int o = 16; o; o >>= 1) cnt += __shfl_xor_sync(0xffffffffu, cnt, o);
    if (lane == 0) {
        g_counts[b] = cnt;
        int tot = past_len[b] + cnt;
        g_totals[b] = tot;
        out_len[b] = (float)tot;
    }
}

// ---------------------------------------------------------------------------
// Kernel 1b: build the attention work queue, longest batches first (LPT).
// ---------------------------------------------------------------------------
__global__ void k_build()
{
    if (threadIdx.x != 0) return;
    g_wctr = 0;
    int ord[B_];
    #pragma unroll
    for (int i = 0; i < B_; i++) ord[i] = i;
    for (int i = 1; i < B_; i++) {         // insertion sort by tot desc
        int j = i;
        while (j > 0 && g_totals[ord[j]] > g_totals[ord[j-1]]) {
            int t = ord[j]; ord[j] = ord[j-1]; ord[j-1] = t; j--;
        }
    }
    int n = 0;
    for (int oi = 0; oi < B_; oi++) {
        int b = ord[oi];
        int nqb = (g_counts[b] + 63) >> 6;
        for (int q = 0; q < nqb; q++)
            for (int h = 0; h < H_; h++)
                g_work[n++] = ((b*H_ + h) << 3) | q;
    }
    g_nwork = n;
}

// ---------------------------------------------------------------------------
// Accurate RoPE angles (fp64 range reduction, fp32 sincos)
// ---------------------------------------------------------------------------
__device__ __forceinline__ void rope_sc(int pos, float fi, float& sn, float& cs)
{
    double f = (double)pos * (double)fi;
    double k = floor(f * 0.15915494309189535);
    float fr = (float)(f - k * 6.283185307179586);
    sincosf(fr, &sn, &cs);
}

// ---------------------------------------------------------------------------
// Shared GEMM body: 128x128 tile, ktile 32, 2-stage cp.async pipeline.
// Inputs are PRE-CONVERTED tf32 -> zero cvt in the loop, raw fragment loads.
// ---------------------------------------------------------------------------
#define GST 36
#define GSTAGE (128*GST)

__device__ __forceinline__ void gemm_pipe(
    const float* __restrict__ Ag, const float* __restrict__ Bg,
    float* sA, float* sB, int tid, float acc[2][8][4])
{
    int warp = tid >> 5, lane = tid & 31;
    int wm = warp >> 1, wn = warp & 1;
    int r0 = lane >> 2, c0 = lane & 3;
    int lrow = tid >> 3;
    int lcol = (tid & 7) * 4;

    #pragma unroll
    for (int it = 0; it < 4; it++) {
        int row = it*32 + lrow;
        cpa16(&sA[row*GST + lcol], &Ag[(size_t)row*DMODEL + lcol]);
        cpa16(&sB[row*GST + lcol], &Bg[(size_t)row*DMODEL + lcol]);
    }
    cpa_commit();

    for (int kt = 0; kt < 32; kt++) {
        int st = (kt & 1) * GSTAGE;
        if (kt + 1 < 32) {
            int ns = ((kt + 1) & 1) * GSTAGE;
            int k0 = (kt + 1) * 32;
            #pragma unroll
            for (int it = 0; it < 4; it++) {
                int row = it*32 + lrow;
                cpa16(&sA[ns + row*GST + lcol], &Ag[(size_t)row*DMODEL + k0 + lcol]);
                cpa16(&sB[ns + row*GST + lcol], &Bg[(size_t)row*DMODEL + k0 + lcol]);
            }
            cpa_commit();
            cpa_wait1();
        } else {
            cpa_wait0();
        }
        __syncthreads();

        #pragma unroll
        for (int ks = 0; ks < 4; ks++) {
            int kk = ks*8;
            unsigned a[2][4], b[8][2];
            #pragma unroll
            for (int mt = 0; mt < 2; mt++) {
                int mr = wm*32 + mt*16 + r0;
                a[mt][0] = U(sA[st + (mr    )*GST + kk + c0]);
                a[mt][1] = U(sA[st + (mr + 8)*GST + kk + c0]);
                a[mt][2] = U(sA[st + (mr    )*GST + kk + 4 + c0]);
                a[mt][3] = U(sA[st + (mr + 8)*GST + kk + 4 + c0]);
            }
            #pragma unroll
            for (int nt = 0; nt < 8; nt++) {
                int nr = wn*64 + nt*8 + r0;
                b[nt][0] = U(sB[st + nr*GST + kk + c0]);
                b[nt][1] = U(sB[st + nr*GST + kk + 4 + c0]);
            }
            #pragma unroll
            for (int mt = 0; mt < 2; mt++)
                #pragma unroll
                for (int nt = 0; nt < 8; nt++)
                    mma8(acc[mt][nt], a[mt], b[nt]);
        }
        __syncthreads();
    }
}

// ---------------------------------------------------------------------------
// Kernel 2: QKV projection (pipelined, zero-cvt). Dead-row blocks exit.
// ---------------------------------------------------------------------------
__global__ __launch_bounds__(256) void k_gemm_qkv(
    const float* __restrict__ bq, const float* __restrict__ bk, const float* __restrict__ bv)
{
    extern __shared__ float smem_g[];
    float* sA = smem_g;
    float* sB = smem_g + 2*GSTAGE;

    int bm = blockIdx.y * 128;
    if ((bm & 511) >= g_counts[bm >> 9]) return;

    int bn = blockIdx.x * 128;
    int seg = bn >> 10;
    const float* bias = (seg == 0) ? bq : ((seg == 1) ? bk : bv);
    int nl = bn & 1023;
    int tid = threadIdx.x;
    int warp = tid >> 5, lane = tid & 31;
    int wm = warp >> 1, wn = warp & 1;
    int r0 = lane >> 2, c0 = lane & 3;

    float acc[2][8][4];
    #pragma unroll
    for (int mt = 0; mt < 2; mt++)
        #pragma unroll
        for (int nt = 0; nt < 8; nt++)
            #pragma unroll
            for (int r = 0; r < 4; r++) acc[mt][nt][r] = 0.f;

    gemm_pipe(g_xt + (size_t)bm*DMODEL,
              g_wt + (size_t)seg*WSZ + (size_t)nl*DMODEL,
              sA, sB, tid, acc);

    #pragma unroll
    for (int mt = 0; mt < 2; mt++) {
        #pragma unroll
        for (int nt = 0; nt < 8; nt++) {
            int row = bm + wm*32 + mt*16 + r0;
            int col = bn + wn*64 + nt*8 + 2*c0;
            float bx = bias[col & 1023], by = bias[(col+1) & 1023];
            float2 v0 = { acc[mt][nt][0] + bx, acc[mt][nt][1] + by };
            float2 v1 = { acc[mt][nt][2] + bx, acc[mt][nt][3] + by };
            *(float2*)&g_qkv[(size_t)row*QKVN + col]     = v0;
            *(float2*)&g_qkv[(size_t)(row+8)*QKVN + col] = v1;
        }
    }
}

// ---------------------------------------------------------------------------
// Kernel 3 (fused): assemble k_total/v_total + RoPE on q.
// ---------------------------------------------------------------------------
__global__ __launch_bounds__(256) void k_prep(
    const float* __restrict__ pastk, const float* __restrict__ pastv,
    const float* __restrict__ invf, const int* __restrict__ past_len,
    float* __restrict__ out)
{
    int bh = blockIdx.y; int b = bh >> 4; int h = bh & 15;
    int gid = blockIdx.x * 256 + threadIdx.x;
    int i = gid & 31; int s = gid >> 5;
    int pl = past_len[b]; int tot = g_totals[b]; int cnt = g_counts[b];
    float k0, k1, v0, v1;
    if (s < pl) {
        size_t base = ((size_t)bh*CACHED + s) * DH;
        k0 = pastk[base + i]; k1 = pastk[base + i + 32];
        v0 = pastv[base + i]; v1 = pastv[base + i + 32];
    } else if (s < tot) {
        int t = s - pl;
        size_t m = (size_t)(b*TNEW + t) * QKVN;
        float sn, cs; rope_sc(s, invf[i], sn, cs);
        float x0 = g_qkv[m + 1024 + h*DH + i];
        float x1 = g_qkv[m + 1024 + h*DH + i + 32];
        k0 = x0*cs - x1*sn;
        k1 = x1*cs + x0*sn;
        v0 = g_qkv[m + 2048 + h*DH + i];
        v1 = g_qkv[m + 2048 + h*DH + i + 32];
    } else {
        k0 = k1 = v0 = v1 = 0.f;
    }
    size_t base = ((size_t)bh*TTOTAL + s) * DH;
    out[OFF_K + base + i]      = k0;
    out[OFF_K + base + i + 32] = k1;
    out[OFF_V + base + i]      = v0;
    out[OFF_V + base + i + 32] = v1;
    if (s < ((tot + 63) & ~63)) {        // attention reads only < roundup(tot,64)
        g_kt[base + i]      = t32(k0);
        g_kt[base + i + 32] = t32(k1);
        g_vt[base + i]      = t32(v0);
        g_vt[base + i + 32] = t32(v1);
    }

    if (s < TNEW) {
        int t = s;
        float o0 = 0.f, o1 = 0.f;
        if (t < cnt) {
            int pos = pl + t;
            float sn, cs; rope_sc(pos, invf[i], sn, cs);
            size_t m = (size_t)(b*TNEW + t) * QKVN + h*DH;
            float x0 = g_qkv[m + i];
            float x1 = g_qkv[m + i + 32];
            o0 = t32(x0*cs - x1*sn) * 0.125f;
            o1 = t32(x1*cs + x0*sn) * 0.125f;
        }
        size_t qb = ((size_t)bh*TNEW + t) * DH;
        g_q[qb + i]      = o0;
        g_q[qb + i + 32] = o1;
    }
}

// ---------------------------------------------------------------------------
// Kernel 4: PERSISTENT flash attention. 444 CTAs (one full wave at 3/SM)
// pull (bh, qblock) items from a queue ordered longest-batch-first.
// Per-item body identical to R13 (K dbl-buffer cp.async, V single, Ps smem).
// ---------------------------------------------------------------------------
#define AT 68
#define KVTILE (64*AT)
#define NPERS  444

__global__ __launch_bounds__(128, 3) void k_attn()
{
    extern __shared__ float sm[];
    float* Kb[2] = { sm, sm + KVTILE };
    float* Vs = sm + 2*KVTILE;
    float (*Ps)[AT] = (float(*)[AT])(sm + 3*KVTILE);
    __shared__ int sm_w;

    int tid = threadIdx.x;
    int warp = tid >> 5, lane = tid & 31;
    int r0 = lane >> 2, c0 = lane & 3;
    int prow = tid >> 4;
    int pcol = (tid & 15) * 4;
    int nwork = g_nwork;

    for (;;) {
        if (tid == 0) sm_w = atomicAdd(&g_wctr, 1);
        __syncthreads();                 // broadcast + protect smem reuse
        int w = sm_w;
        if (w >= nwork) return;
        int item = g_work[w];
        int bh = item >> 3;
        int b = bh >> 4;
        int qb = (item & 7) << 6;

        int tot = g_totals[b];
        int nkb = (tot + 63) >> 6;
        const float* kbase = g_kt + (size_t)bh*TTOTAL*DH;
        const float* vbase = g_vt + (size_t)bh*TTOTAL*DH;

        #pragma unroll
        for (int j = 0; j < 8; j++) {
            int row = j*8 + prow;
            cpa16(&Kb[0][row*AT + pcol], &kbase[(size_t)row*DH + pcol]);
        }
        cpa_commit();

        {
            const float* qp = g_q + ((size_t)bh*TNEW + qb) * DH;
            #pragma unroll
            for (int j = 0; j < 8; j++) {
                int id = j*128 + tid;
                int row = id >> 4;
                int c = (id & 15) * 4;
                *(float4*)&Ps[row][c] = *(const float4*)&qp[(size_t)row*DH + c];
            }
        }
        __syncthreads();

        unsigned qa[8][4];
        int qr = warp*16 + r0;
        #pragma unroll
        for (int ks = 0; ks < 8; ks++) {
            qa[ks][0] = U(Ps[qr  ][ks*8 + c0]);
            qa[ks][1] = U(Ps[qr+8][ks*8 + c0]);
            qa[ks][2] = U(Ps[qr  ][ks*8 + 4 + c0]);
            qa[ks][3] = U(Ps[qr+8][ks*8 + 4 + c0]);
        }

        float oacc[8][4];
        #pragma unroll
        for (int nt = 0; nt < 8; nt++)
            #pragma unroll
            for (int r = 0; r < 4; r++) oacc[nt][r] = 0.f;
        float mrow0 = -1e30f, mrow1 = -1e30f, lrow0 = 0.f, lrow1 = 0.f;

        for (int kb = 0; kb < nkb; kb++) {
            cpa_wait0();
            __syncthreads();

            {
                const float* vg = vbase + (size_t)kb*64*DH;
                #pragma unroll
                for (int j = 0; j < 8; j++) {
                    int row = j*8 + prow;
                    cpa16(&Vs[row*AT + pcol], &vg[(size_t)row*DH + pcol]);
                }
                cpa_commit();
            }
            bool havek = (kb + 1 < nkb);
            if (havek) {
                int nb = (kb + 1) & 1;
                const float* kg = kbase + (size_t)(kb+1)*64*DH;
                #pragma unroll
                for (int j = 0; j < 8; j++) {
                    int row = j*8 + prow;
                    cpa16(&Kb[nb][row*AT + pcol], &kg[(size_t)row*DH + pcol]);
                }
                cpa_commit();
            }

            const float* Ks = Kb[kb & 1];

            float sacc[8][4];
            #pragma unroll
            for (int nt = 0; nt < 8; nt++)
                #pragma unroll
                for (int r = 0; r < 4; r++) sacc[nt][r] = 0.f;
            #pragma unroll
            for (int ks = 0; ks < 8; ks++) {
                #pragma unroll
                for (int nt = 0; nt < 8; nt++) {
                    unsigned bb[2];
                    bb[0] = U(Ks[(nt*8 + r0)*AT + ks*8 + c0]);
                    bb[1] = U(Ks[(nt*8 + r0)*AT + ks*8 + 4 + c0]);
                    mma8(sacc[nt], qa[ks], bb);
                }
            }

            if (kb == nkb - 1) {
                #pragma unroll
                for (int nt = 0; nt < 8; nt++) {
                    int col = kb*64 + nt*8 + 2*c0;
                    if (col     >= tot) { sacc[nt][0] = -1e30f; sacc[nt][2] = -1e30f; }
                    if (col + 1 >= tot) { sacc[nt][1] = -1e30f; sacc[nt][3] = -1e30f; }
                }
            }

            float ml0 = -1e30f, ml1 = -1e30f;
            #pragma unroll
            for (int nt = 0; nt < 8; nt++) {
                ml0 = fmaxf(ml0, fmaxf(sacc[nt][0], sacc[nt][1]));
                ml1 = fmaxf(ml1, fmaxf(sacc[nt][2], sacc[nt][3]));
            }
            ml0 = fmaxf(ml0, __shfl_xor_sync(0xffffffffu, ml0, 1));
            ml0 = fmaxf(ml0, __shfl_xor_sync(0xffffffffu, ml0, 2));
            ml1 = fmaxf(ml1, __shfl_xor_sync(0xffffffffu, ml1, 1));
            ml1 = fmaxf(ml1, __shfl_xor_sync(0xffffffffu, ml1, 2));

            float mn0 = fmaxf(mrow0, ml0), mn1 = fmaxf(mrow1, ml1);
            float e0 = __expf(mrow0 - mn0), e1 = __expf(mrow1 - mn1);
            mrow0 = mn0; mrow1 = mn1;

            float ls0 = 0.f, ls1 = 0.f;
            #pragma unroll
            for (int nt = 0; nt < 8; nt++) {
                float p0 = __expf(sacc[nt][0] - mn0);
                float p1 = __expf(sacc[nt][1] - mn0);
                float p2 = __expf(sacc[nt][2] - mn1);
                float p3 = __expf(sacc[nt][3] - mn1);
                ls0 += p0 + p1; ls1 += p2 + p3;
                float2 w0 = { t32(p0), t32(p1) };
                float2 w1 = { t32(p2), t32(p3) };
                *(float2*)&Ps[warp*16 + r0    ][nt*8 + 2*c0] = w0;
                *(float2*)&Ps[warp*16 + r0 + 8][nt*8 + 2*c0] = w1;
                oacc[nt][0] *= e0; oacc[nt][1] *= e0;
                oacc[nt][2] *= e1; oacc[nt][3] *= e1;
            }
            ls0 += __shfl_xor_sync(0xffffffffu, ls0, 1);
            ls0 += __shfl_xor_sync(0xffffffffu, ls0, 2);
            ls1 += __shfl_xor_sync(0xffffffffu, ls1, 1);
            ls1 += __shfl_xor_sync(0xffffffffu, ls1, 2);
            lrow0 = lrow0*e0 + ls0;
            lrow1 = lrow1*e1 + ls1;

            if (havek) cpa_wait1(); else cpa_wait0();
            __syncthreads();

            #pragma unroll
            for (int ks = 0; ks < 8; ks++) {
                unsigned pa[4];
                pa[0] = U(Ps[warp*16 + r0    ][ks*8 + c0]);
                pa[1] = U(Ps[warp*16 + r0 + 8][ks*8 + c0]);
                pa[2] = U(Ps[warp*16 + r0    ][ks*8 + 4 + c0]);
                pa[3] = U(Ps[warp*16 + r0 + 8][ks*8 + 4 + c0]);
                #pragma unroll
                for (int nt = 0; nt < 8; nt++) {
                    unsigned bb[2];
                    bb[0] = U(Vs[(ks*8 + c0    )*AT + nt*8 + r0]);
                    bb[1] = U(Vs[(ks*8 + 4 + c0)*AT + nt*8 + r0]);
                    mma8(oacc[nt], pa, bb);
                }
            }
        }

        // finalize this item
        float inv0 = 1.f / lrow0, inv1 = 1.f / lrow1;
        float* op = g_ctx + ((size_t)b*TNEW + qb + warp*16) * DMODEL + (bh & 15)*DH;
        #pragma unroll
        for (int nt = 0; nt < 8; nt++) {
            int col = nt*8 + 2*c0;
            float2 v0 = { t32(oacc[nt][0]*inv0), t32(oacc[nt][1]*inv0) };
            float2 v1 = { t32(oacc[nt][2]*inv1), t32(oacc[nt][3]*inv1) };
            *(float2*)&op[(size_t)r0*DMODEL + col]       = v0;
            *(float2*)&op[(size_t)(r0+8)*DMODEL + col]   = v1;
        }
    }
}

// ---------------------------------------------------------------------------
// Kernel 5: output projection (pipelined, zero-cvt) + valid-token mask.
// ---------------------------------------------------------------------------
__global__ __launch_bounds__(256) void k_gemm_out(
    const float* __restrict__ bo, float* __restrict__ out)
{
    extern __shared__ float smem_g[];
    float* sA = smem_g;
    float* sB = smem_g + 2*GSTAGE;

    int bm = blockIdx.y * 128;
    int bn = blockIdx.x * 128;
    int tid = threadIdx.x;

    if ((bm & 511) >= g_counts[bm >> 9]) {
        float4 z = {0.f, 0.f, 0.f, 0.f};
        #pragma unroll
        for (int j = 0; j < 16; j++) {
            int id = j*256 + tid;
            int row = id >> 5;
            int col = (id & 31) * 4;
            *(float4*)&out[(size_t)(bm + row)*DMODEL + bn + col] = z;
        }
        return;
    }

    int warp = tid >> 5, lane = tid & 31;
    int wm = warp >> 1, wn = warp & 1;
    int r0 = lane >> 2, c0 = lane & 3;

    float acc[2][8][4];
    #pragma unroll
    for (int mt = 0; mt < 2; mt++)
        #pragma unroll
        for (int nt = 0; nt < 8; nt++)
            #pragma unroll
            for (int r = 0; r < 4; r++) acc[mt][nt][r] = 0.f;

    gemm_pipe(g_ctx + (size_t)bm*DMODEL,
              g_wt + (size_t)3*WSZ + (size_t)bn*DMODEL,
              sA, sB, tid, acc);

    #pragma unroll
    for (int mt = 0; mt < 2; mt++) {
        int row = bm + wm*32 + mt*16 + r0;
        int bb0 = (row)     >> 9, tt0 = (row)     & 511;
        int bb1 = (row + 8) >> 9, tt1 = (row + 8) & 511;
        float m0 = (tt0 < g_counts[bb0]) ? 1.f : 0.f;
        float m1 = (tt1 < g_counts[bb1]) ? 1.f : 0.f;
        #pragma unroll
        for (int nt = 0; nt < 8; nt++) {
            int col = bn + wn*64 + nt*8 + 2*c0;
            float bx = bo[col], by = bo[col+1];
            float2 v0 = { (acc[mt][nt][0] + bx)*m0, (acc[mt][nt][1] + by)*m0 };
            float2 v1 = { (acc[mt][nt][2] + bx)*m1, (acc[mt][nt][3] + by)*m1 };
            *(float2*)&out[(size_t)row*DMODEL + col]     = v0;
            *(float2*)&out[(size_t)(row+8)*DMODEL + col] = v1;
        }
    }
}

// ---------------------------------------------------------------------------
extern "C" void kernel_launch(void* const* d_in, const int* in_sizes, int n_in,
                              void* d_out, int out_size)
{
    const float* x     = (const float*)d_in[0];
    const float* invf  = (const float*)d_in[1];
    const float* pastk = (const float*)d_in[2];
    const float* pastv = (const float*)d_in[3];
    const float* Wq    = (const float*)d_in[4];
    const float* bq    = (const float*)d_in[5];
    const float* Wk    = (const float*)d_in[6];
    const float* bk    = (const float*)d_in[7];
    const float* Wv    = (const float*)d_in[8];
    const float* bv    = (const float*)d_in[9];
    const float* Wo    = (const float*)d_in[10];
    const float* bo    = (const float*)d_in[11];
    const int* past_len = (const int*)d_in[13];
    const unsigned char* vmask = (const unsigned char*)d_in[14];
    float* out = (float*)d_out;

    int gsmem = 4*GSTAGE*4;  // 73728 B
    cudaFuncSetAttribute(k_gemm_qkv, cudaFuncAttributeMaxDynamicSharedMemorySize, gsmem);
    cudaFuncSetAttribute(k_gemm_out, cudaFuncAttributeMaxDynamicSharedMemorySize, gsmem);

    k_setup<<<B_, 32>>>(vmask, past_len, out + OFF_LEN);
    k_build<<<1, 32>>>();
    k_cvt<<<(MROWS*DMODEL + 4*WSZ)/4/256, 256>>>(x, Wq, Wk, Wv, Wo);
    k_gemm_qkv<<<dim3(QKVN/128, MROWS/128), 256, gsmem>>>(bq, bk, bv);
    k_prep<<<dim3(TTOTAL*32/256, B_*H_), 256>>>(pastk, pastv, invf, past_len, out);

    int smem = (3*KVTILE + 64*AT) * 4;   // 69632 -> 3 CTAs/SM
    cudaFuncSetAttribute(k_attn, cudaFuncAttributeMaxDynamicSharedMemorySize, smem);
    k_attn<<<NPERS, 128, smem>>>();

    k_gemm_out<<<dim3(DMODEL/128, MROWS/128), 256, gsmem>>>(bo, out);
}